// round 13
// baseline (speedup 1.0000x reference)
#include <cuda_runtime.h>
#include <cuda_bf16.h>

// RFCM loss — fused single pass, barrier-free stencil, f32x2 packed.
//   mem = y_pred^2
//   J1 total = sum_{b,k} (A - B^2/C),  A=Σ mem*img^2, B=Σ mem*img, C=Σ mem
//   J2 = Σ_z [ BS(z)·M3S(z) − MS(z)² − Σ_k b_k(z)·m3_k(z) + Σ_k m_k(z)² ]
//     b_k = 2D 3x3 box at plane z, m3_k(z) = m_k(z−1)+m_k(z)+m_k(z+1)
//     (z-adjoint of the 3D box: only ONE box plane live at a time)
//   out = (ΣJ1 + 8e-4·ΣJ2) / (B*N)
//
// Each warp owns a full x-row (32 lanes × float4) and loads its THREE y-rows
// (y-1, y, y+1) directly: 2D box = xtap(ytap) — y-sum in packed f32x2, then
// one x 3-tap via 2 shuffles per cluster. No smem exchange, ZERO barriers in
// the main loop; redundant row reads are L1 hits (plane working set 20KB).
// z via register history, z-loop fully unrolled. Deterministic last-block
// finalize.

namespace {
constexpr int TY   = 8;
constexpr int CZ   = 16;
constexpr int NTH  = 32 * TY;         // 256
constexpr int NVOX = 128 * 128 * 128;
constexpr int PL   = 128 * 128;       // z-plane stride (floats)
constexpr int GYB  = 128 / TY;        // 16
constexpr int GZB  = 128 / CZ;        // 8
constexpr int NBLK = GYB * GZB * 2;   // 256
}

__device__ float g_part[NBLK * 13];
__device__ unsigned int g_count;      // zero-init; reset by finalizer each launch

// ---- packed f32x2 helpers (sm_103a FFMA2 path; PTX-only) ----
struct P2 { unsigned long long v; };
struct Q  { P2 a, b; };               // a = lanes (0,1), b = lanes (2,3)

__device__ __forceinline__ P2 pk(float lo, float hi) {
    P2 r; asm("mov.b64 %0, {%1, %2};" : "=l"(r.v) : "f"(lo), "f"(hi)); return r;
}
__device__ __forceinline__ void upk(P2 a, float& lo, float& hi) {
    asm("mov.b64 {%0, %1}, %2;" : "=f"(lo), "=f"(hi) : "l"(a.v));
}
__device__ __forceinline__ P2 padd(P2 a, P2 b) {
    P2 r; asm("add.rn.f32x2 %0, %1, %2;" : "=l"(r.v) : "l"(a.v), "l"(b.v)); return r;
}
__device__ __forceinline__ P2 pmul(P2 a, P2 b) {
    P2 r; asm("mul.rn.f32x2 %0, %1, %2;" : "=l"(r.v) : "l"(a.v), "l"(b.v)); return r;
}
__device__ __forceinline__ P2 pfma(P2 a, P2 b, P2 c) {
    P2 r; asm("fma.rn.f32x2 %0, %1, %2, %3;"
              : "=l"(r.v) : "l"(a.v), "l"(b.v), "l"(c.v)); return r;
}
__device__ __forceinline__ P2 pneg(P2 a) {
    P2 r; asm("xor.b64 %0, %1, 0x8000000080000000;" : "=l"(r.v) : "l"(a.v)); return r;
}
__device__ __forceinline__ P2 pzero() { P2 r; r.v = 0ull; return r; }
__device__ __forceinline__ float psum(P2 a) { float lo, hi; upk(a, lo, hi); return lo + hi; }

struct R2 { P2 a, b; };               // one float4 worth, as two packed pairs
__device__ __forceinline__ R2 r2zero() { R2 r; r.a = pzero(); r.b = pzero(); return r; }

__global__ void __launch_bounds__(NTH, 2)
rfcm(const float* __restrict__ yp, const float* __restrict__ img,
     float* __restrict__ out) {
    __shared__ float red[TY * 13];
    __shared__ unsigned amLast;
    const int lane = threadIdx.x, wy = threadIdx.y;
    const int tid  = wy * 32 + lane;
    const int gy0  = blockIdx.x * TY;
    const int z0   = blockIdx.y * CZ;
    const int b    = blockIdx.z;
    const int x0   = lane * 4;
    const int y    = gy0 + wy;
    const bool y0ok = (y > 0), y1ok = (y < 127);

    const float* pb[4];
    #pragma unroll
    for (int k = 0; k < 4; ++k)
        pb[k] = yp + (size_t)b * 4 * NVOX + (size_t)k * NVOX + (size_t)y * 128 + x0;
    const float* pim = img + (size_t)b * NVOX + (size_t)y * 128 + x0;

    auto ld2 = [](const float* p) -> R2 {
        ulonglong2 u = __ldg(reinterpret_cast<const ulonglong2*>(p));
        R2 r; r.a.v = u.x; r.b.v = u.y; return r;
    };

    // full plane: per cluster, 3 y-rows -> squared -> y-sum (packed) ->
    // x 3-tap via shuffles -> box; center row squared -> m.
    auto plane = [&](int zp, Q box[4], Q m[4]) {
        #pragma unroll
        for (int k = 0; k < 4; ++k) {
            const float* p = pb[k] + (size_t)zp * PL;
            R2 u1 = ld2(p);
            R2 u0 = y0ok ? ld2(p - 128) : r2zero();
            R2 u2 = y1ok ? ld2(p + 128) : r2zero();
            P2 s1a = pmul(u1.a, u1.a), s1b = pmul(u1.b, u1.b);
            m[k].a = s1a; m[k].b = s1b;
            P2 ya = padd(padd(pmul(u0.a, u0.a), s1a), pmul(u2.a, u2.a));
            P2 yb = padd(padd(pmul(u0.b, u0.b), s1b), pmul(u2.b, u2.b));
            float yx, yy, yz, yw;
            upk(ya, yx, yy); upk(yb, yz, yw);
            float left  = __shfl_up_sync(0xffffffffu, yw, 1);
            float right = __shfl_down_sync(0xffffffffu, yx, 1);
            if (lane == 0)  left  = 0.f;
            if (lane == 31) right = 0.f;
            float t1 = yx + yy, t2 = yz + yw;
            box[k].a = pk(left + t1, t1 + yz);
            box[k].b = pk(yy + t2, t2 + right);
        }
    };
    auto centers = [&](int zp, Q m[4]) {          // z-halo plane: m only
        const bool zin = ((unsigned)zp < 128u);
        #pragma unroll
        for (int k = 0; k < 4; ++k) {
            R2 u = zin ? ld2(pb[k] + (size_t)zp * PL) : r2zero();
            m[k].a = pmul(u.a, u.a); m[k].b = pmul(u.b, u.b);
        }
    };

    Q m1[4], m2[4], bprev[4];
    #pragma unroll
    for (int k = 0; k < 4; ++k) {
        m1[k].a = pzero(); m1[k].b = pzero();
        bprev[k].a = pzero(); bprev[k].b = pzero();
    }
    P2 A2[4], B2[4], C2[4];
    #pragma unroll
    for (int k = 0; k < 4; ++k) { A2[k] = pzero(); B2[k] = pzero(); C2[k] = pzero(); }
    P2 j2a = pzero(), j2b = pzero();

    centers(z0 - 1, m2);              // m2 = m(z0-1)

    auto j2step = [&](const Q mnew[4]) {   // J2 at plane z: bprev=b(z), m2=m(z)
        P2 M3a = pzero(), M3b = pzero(), BSa = pzero(), BSb = pzero();
        P2 MSa = pzero(), MSb = pzero();
        P2 t1a = pzero(), t1b = pzero(), t2a = pzero(), t2b = pzero();
        #pragma unroll
        for (int k = 0; k < 4; ++k) {
            P2 m3a = padd(padd(m1[k].a, m2[k].a), mnew[k].a);
            P2 m3b = padd(padd(m1[k].b, m2[k].b), mnew[k].b);
            M3a = padd(M3a, m3a);          M3b = padd(M3b, m3b);
            BSa = padd(BSa, bprev[k].a);   BSb = padd(BSb, bprev[k].b);
            MSa = padd(MSa, m2[k].a);      MSb = padd(MSb, m2[k].b);
            t1a = pfma(bprev[k].a, m3a, t1a); t1b = pfma(bprev[k].b, m3b, t1b);
            t2a = pfma(m2[k].a, m2[k].a, t2a); t2b = pfma(m2[k].b, m2[k].b, t2b);
        }
        j2a = pfma(BSa, M3a, j2a); j2a = pfma(pneg(MSa), MSa, j2a);
        j2a = padd(j2a, padd(t2a, pneg(t1a)));
        j2b = pfma(BSb, M3b, j2b); j2b = pfma(pneg(MSb), MSb, j2b);
        j2b = padd(j2b, padd(t2b, pneg(t1b)));
    };

    #pragma unroll
    for (int i = 0; i < CZ; ++i) {    // p = z0 + i, always in [0,128)
        const int p = z0 + i;
        Q bnew[4], mnew[4];
        plane(p, bnew, mnew);
        R2 iv = ld2(pim + (size_t)p * PL);
        P2 i2a = pmul(iv.a, iv.a), i2b = pmul(iv.b, iv.b);
        #pragma unroll
        for (int k = 0; k < 4; ++k) {  // ABC at plane p
            C2[k] = padd(C2[k], padd(mnew[k].a, mnew[k].b));
            B2[k] = pfma(mnew[k].a, iv.a, pfma(mnew[k].b, iv.b, B2[k]));
            A2[k] = pfma(mnew[k].a, i2a,  pfma(mnew[k].b, i2b,  A2[k]));
        }
        if (i > 0) j2step(mnew);       // J2 at z = p-1
        #pragma unroll
        for (int k = 0; k < 4; ++k) { bprev[k] = bnew[k]; m1[k] = m2[k]; m2[k] = mnew[k]; }
    }
    {                                  // epilogue: J2 at z0+CZ-1 needs m(z0+CZ)
        Q mnew[4];
        centers(z0 + CZ, mnew);
        j2step(mnew);
    }

    // ---- block reduction: 13 scalars ----
    float vals[13];
    #pragma unroll
    for (int k = 0; k < 4; ++k) {
        vals[k]     = psum(A2[k]);
        vals[4 + k] = psum(B2[k]);
        vals[8 + k] = psum(C2[k]);
    }
    vals[12] = psum(j2a) + psum(j2b);
    #pragma unroll
    for (int off = 16; off; off >>= 1)
        #pragma unroll
        for (int j = 0; j < 13; ++j)
            vals[j] += __shfl_down_sync(0xffffffffu, vals[j], off);

    if (lane == 0) {
        #pragma unroll
        for (int j = 0; j < 13; ++j) red[wy * 13 + j] = vals[j];
    }
    __syncthreads();
    const int blockid = blockIdx.x + GYB * blockIdx.y + (GYB * GZB) * blockIdx.z;
    if (tid < 13) {
        float s = 0.f;
        #pragma unroll
        for (int w = 0; w < TY; ++w) s += red[w * 13 + tid];
        g_part[blockid * 13 + tid] = s;
    }

    // ---- deterministic last-block finalize ----
    __threadfence();
    if (tid == 0) amLast = (atomicAdd(&g_count, 1u) == (unsigned)(NBLK - 1)) ? 1u : 0u;
    __syncthreads();
    if (amLast) {
        __threadfence();                   // acquire all g_part writes
        if (tid == 0) g_count = 0;         // reset for next graph replay
        float v[13];                       // entry e = tid; 0..127 b0, 128..255 b1
        const float* pp = &g_part[tid * 13];
        #pragma unroll
        for (int j = 0; j < 13; ++j) v[j] = pp[j];
        #pragma unroll
        for (int off = 16; off; off >>= 1)
            #pragma unroll
            for (int j = 0; j < 13; ++j)
                v[j] += __shfl_down_sync(0xffffffffu, v[j], off);
        if (lane == 0) {
            #pragma unroll
            for (int j = 0; j < 13; ++j) red[wy * 13 + j] = v[j];
        }
        __syncthreads();
        if (tid == 0) {
            float J1 = 0.f, J2t = 0.f;
            #pragma unroll
            for (int b2 = 0; b2 < 2; ++b2) {
                float s[13];
                #pragma unroll
                for (int j = 0; j < 13; ++j)
                    s[j] = red[(b2 * 4 + 0) * 13 + j] + red[(b2 * 4 + 1) * 13 + j] +
                           red[(b2 * 4 + 2) * 13 + j] + red[(b2 * 4 + 3) * 13 + j];
                #pragma unroll
                for (int k = 0; k < 4; ++k)
                    J1 += s[k] - s[4 + k] * s[4 + k] / s[8 + k];
                J2t += s[12];
            }
            out[0] = (J1 + 0.0008f * J2t) * (1.0f / (2.0f * (float)NVOX));
        }
    }
}

extern "C" void kernel_launch(void* const* d_in, const int* in_sizes, int n_in,
                              void* d_out, int out_size) {
    const float* yp  = (const float*)d_in[0];  // y_pred [2,4,128,128,128] f32
    const float* img = (const float*)d_in[1];  // image  [2,1,128,128,128] f32
    float* out = (float*)d_out;                // scalar f32

    rfcm<<<dim3(GYB, GZB, 2), dim3(32, TY)>>>(yp, img, out);
}

// round 14
// speedup vs baseline: 1.1493x; 1.1493x over previous
#include <cuda_runtime.h>
#include <cuda_bf16.h>

// RFCM loss, fused single-pass, separable + z-adjoint formulation, f32x2 packed.
//   mem = y_pred^2
//   J1 total = sum_{b,k} (A - B^2/C),  A=Σ mem*img^2, B=Σ mem*img, C=Σ mem
//   J2 = Σ_z [ BS(z)·M3S(z) − MS(z)² − Σ_k b_k(z)·m3_k(z) + Σ_k m_k(z)² ]
//     b_k = 2D 3x3 box at plane z, m3_k(z) = m_k(z−1)+m_k(z)+m_k(z+1)
//   out = (ΣJ1 + 8e-4·ΣJ2) / (B*N)
//
// R10 structure (proven 26.2us): warp = full x row (32 lanes × float4), x 3-tap
// via shuffles, rowsums in double-buffered smem, y 3-tap via LDS.128, z via
// register history, one-plane prefetch, f32x2 packed math, full unroll.
// This round: (1) commit keeps own-row rowsum in registers -> colsum reads
// only 2 neighbor rows (LDS 12->8 per warp-plane); (2) CZ=8 -> 512 blocks for
// finer scheduler granularity / tail balance. Deterministic last-block finalize.

namespace {
constexpr int TY   = 8;
constexpr int CZ   = 8;
constexpr int NTH  = 32 * TY;         // 256
constexpr int NVOX = 128 * 128 * 128;
constexpr int PL   = 128 * 128;       // z-plane stride (floats)
constexpr int GYB  = 128 / TY;        // 16
constexpr int GZB  = 128 / CZ;        // 16
constexpr int NBLK = GYB * GZB * 2;   // 512
}

__device__ float g_part[NBLK * 13];
__device__ unsigned int g_count;      // zero-init; reset by finalizer each launch

// ---- packed f32x2 helpers (sm_103a FFMA2 path; PTX-only) ----
struct P2 { unsigned long long v; };
struct Q  { P2 a, b; };               // a = lanes (0,1), b = lanes (2,3)

__device__ __forceinline__ P2 pk(float lo, float hi) {
    P2 r; asm("mov.b64 %0, {%1, %2};" : "=l"(r.v) : "f"(lo), "f"(hi)); return r;
}
__device__ __forceinline__ void upk(P2 a, float& lo, float& hi) {
    asm("mov.b64 {%0, %1}, %2;" : "=f"(lo), "=f"(hi) : "l"(a.v));
}
__device__ __forceinline__ P2 padd(P2 a, P2 b) {
    P2 r; asm("add.rn.f32x2 %0, %1, %2;" : "=l"(r.v) : "l"(a.v), "l"(b.v)); return r;
}
__device__ __forceinline__ P2 pmul(P2 a, P2 b) {
    P2 r; asm("mul.rn.f32x2 %0, %1, %2;" : "=l"(r.v) : "l"(a.v), "l"(b.v)); return r;
}
__device__ __forceinline__ P2 pfma(P2 a, P2 b, P2 c) {
    P2 r; asm("fma.rn.f32x2 %0, %1, %2, %3;"
              : "=l"(r.v) : "l"(a.v), "l"(b.v), "l"(c.v)); return r;
}
__device__ __forceinline__ P2 pneg(P2 a) {
    P2 r; asm("xor.b64 %0, %1, 0x8000000080000000;" : "=l"(r.v) : "l"(a.v)); return r;
}
__device__ __forceinline__ P2 pzero() { P2 r; r.v = 0ull; return r; }
__device__ __forceinline__ float psum(P2 a) { float lo, hi; upk(a, lo, hi); return lo + hi; }
__device__ __forceinline__ P2 u2a(ulonglong2 u) { P2 r; r.v = u.x; return r; }
__device__ __forceinline__ P2 u2b(ulonglong2 u) { P2 r; r.v = u.y; return r; }

__global__ void __launch_bounds__(NTH, 2)
rfcm(const float* __restrict__ yp, const float* __restrict__ img,
     float* __restrict__ out) {
    __shared__ __align__(16) float sb[2][4][TY + 2][128];  // rowsum planes, 2-buf
    __shared__ float red[TY * 26];
    __shared__ unsigned amLast;
    const int lane = threadIdx.x, wy = threadIdx.y;
    const int tid  = wy * 32 + lane;
    const int gy0  = blockIdx.x * TY;
    const int z0   = blockIdx.y * CZ;
    const int b    = blockIdx.z;
    const int x0   = lane * 4;
    // halo: 2 rows × 4 clusters = 8 units, one per warp → zero divergence
    const int  hk   = wy & 3;
    const int  hrow = (wy < 4) ? 0 : (TY + 1);
    const int  hy   = (wy < 4) ? (gy0 - 1) : (gy0 + TY);
    const bool hin  = ((unsigned)hy < 128u);

    const float* ypb = yp  + (size_t)b * 4 * NVOX;
    const float* pc[4];
    #pragma unroll
    for (int k = 0; k < 4; ++k)
        pc[k] = ypb + (size_t)k * NVOX + (size_t)(gy0 + wy) * 128 + x0;
    const float* ph  = ypb + (size_t)hk * NVOX + (size_t)(hin ? hy : 0) * 128 + x0;
    const float* pim = img + (size_t)b * NVOX + (size_t)(gy0 + wy) * 128 + x0;

    float4 rc[4], rh;                 // prefetched raw plane
    auto issue = [&](int zp) {
        const bool zin = ((unsigned)zp < 128u);
        const float4 z4 = make_float4(0.f, 0.f, 0.f, 0.f);
        #pragma unroll
        for (int k = 0; k < 4; ++k)
            rc[k] = zin ? __ldg(reinterpret_cast<const float4*>(pc[k] + (size_t)zp * PL)) : z4;
        rh = (zin && hin) ? __ldg(reinterpret_cast<const float4*>(ph + (size_t)zp * PL)) : z4;
    };
    auto ldimg = [&](int zp) -> Q {
        ulonglong2 u = __ldg(reinterpret_cast<const ulonglong2*>(pim + (size_t)zp * PL));
        Q q; q.a = u2a(u); q.b = u2b(u); return q;
    };
    auto rowsum4 = [&](float x, float y, float z, float w) -> float4 {
        float left  = __shfl_up_sync(0xffffffffu, w, 1);
        float right = __shfl_down_sync(0xffffffffu, x, 1);
        if (lane == 0)  left  = 0.f;
        if (lane == 31) right = 0.f;
        float t1 = x + y, t2 = z + w;
        return make_float4(left + t1, t1 + z, y + t2, t2 + right);
    };
    // square + rowsum + store + 1 barrier; own-row rowsum also kept in regs
    auto commit = [&](int par, Q mnew[4], Q rsown[4]) {
        #pragma unroll
        for (int k = 0; k < 4; ++k) {
            float x = rc[k].x * rc[k].x, y = rc[k].y * rc[k].y;
            float z = rc[k].z * rc[k].z, w = rc[k].w * rc[k].w;
            float4 rs = rowsum4(x, y, z, w);
            *reinterpret_cast<float4*>(&sb[par][k][wy + 1][x0]) = rs;
            rsown[k].a = pk(rs.x, rs.y); rsown[k].b = pk(rs.z, rs.w);
            mnew[k].a = pk(x, y); mnew[k].b = pk(z, w);
        }
        *reinterpret_cast<float4*>(&sb[par][hk][hrow][x0]) =
            rowsum4(rh.x * rh.x, rh.y * rh.y, rh.z * rh.z, rh.w * rh.w);
        __syncthreads();
    };
    // 2D box = own rowsum (regs) + two neighbor rows (smem): 8 LDS.128
    auto colsum = [&](int par, const Q rsown[4], Q bo[4]) {
        #pragma unroll
        for (int k = 0; k < 4; ++k) {
            ulonglong2 r0 = *reinterpret_cast<const ulonglong2*>(&sb[par][k][wy][x0]);
            ulonglong2 r2 = *reinterpret_cast<const ulonglong2*>(&sb[par][k][wy + 2][x0]);
            bo[k].a = padd(padd(u2a(r0), u2a(r2)), rsown[k].a);
            bo[k].b = padd(padd(u2b(r0), u2b(r2)), rsown[k].b);
        }
    };

    Q m1[4], m2[4], bprev[4];
    #pragma unroll
    for (int k = 0; k < 4; ++k) {
        m1[k].a = pzero(); m1[k].b = pzero();
        bprev[k].a = pzero(); bprev[k].b = pzero();
    }
    P2 A2[4], B2[4], C2[4];
    #pragma unroll
    for (int k = 0; k < 4; ++k) { A2[k] = pzero(); B2[k] = pzero(); C2[k] = pzero(); }
    P2 j2a = pzero(), j2b = pzero();

    // prologue: commit plane z0-1 (m only), prefetch plane z0 + img(z0)
    issue(z0 - 1);
    {
        Q rs0[4];
        commit(0, m2, rs0);           // m2 = m(z0-1); rowsums of z0-1 unused
    }
    issue(z0);
    Q imgc = ldimg(z0);
    Q imgn; imgn.a = pzero(); imgn.b = pzero();

    #pragma unroll
    for (int i = 0; i <= CZ; ++i) {   // p = z0 + i : plane being committed
        const int p   = z0 + i;
        const int par = (i + 1) & 1;

        Q mnew[4], rsown[4];
        commit(par, mnew, rsown);     // consume prefetched raw(p)
        if (i < CZ) issue(p + 1);
        if (i < CZ - 1) imgn = ldimg(p + 1);

        if (i < CZ) {                 // ABC at plane p
            P2 i2a = pmul(imgc.a, imgc.a), i2b = pmul(imgc.b, imgc.b);
            #pragma unroll
            for (int k = 0; k < 4; ++k) {
                C2[k] = padd(C2[k], padd(mnew[k].a, mnew[k].b));
                B2[k] = pfma(mnew[k].a, imgc.a, pfma(mnew[k].b, imgc.b, B2[k]));
                A2[k] = pfma(mnew[k].a, i2a,    pfma(mnew[k].b, i2b,    A2[k]));
            }
        }
        if (i > 0) {                  // J2 at z = p-1 (bprev=b(p-1), m2=m(p-1))
            P2 M3a = pzero(), M3b = pzero(), BSa = pzero(), BSb = pzero();
            P2 MSa = pzero(), MSb = pzero();
            P2 t1a = pzero(), t1b = pzero(), t2a = pzero(), t2b = pzero();
            #pragma unroll
            for (int k = 0; k < 4; ++k) {
                P2 m3a = padd(padd(m1[k].a, m2[k].a), mnew[k].a);
                P2 m3b = padd(padd(m1[k].b, m2[k].b), mnew[k].b);
                M3a = padd(M3a, m3a);          M3b = padd(M3b, m3b);
                BSa = padd(BSa, bprev[k].a);   BSb = padd(BSb, bprev[k].b);
                MSa = padd(MSa, m2[k].a);      MSb = padd(MSb, m2[k].b);
                t1a = pfma(bprev[k].a, m3a, t1a); t1b = pfma(bprev[k].b, m3b, t1b);
                t2a = pfma(m2[k].a, m2[k].a, t2a); t2b = pfma(m2[k].b, m2[k].b, t2b);
            }
            j2a = pfma(BSa, M3a, j2a); j2a = pfma(pneg(MSa), MSa, j2a);
            j2a = padd(j2a, padd(t2a, pneg(t1a)));
            j2b = pfma(BSb, M3b, j2b); j2b = pfma(pneg(MSb), MSb, j2b);
            j2b = padd(j2b, padd(t2b, pneg(t1b)));
        }
        if (i < CZ) colsum(par, rsown, bprev);   // b(p) overwrites bprev
        #pragma unroll
        for (int k = 0; k < 4; ++k) { m1[k] = m2[k]; m2[k] = mnew[k]; }
        imgc = imgn;
    }

    // ---- block reduction: 13 scalars ----
    float vals[13];
    #pragma unroll
    for (int k = 0; k < 4; ++k) {
        vals[k]     = psum(A2[k]);
        vals[4 + k] = psum(B2[k]);
        vals[8 + k] = psum(C2[k]);
    }
    vals[12] = psum(j2a) + psum(j2b);
    #pragma unroll
    for (int off = 16; off; off >>= 1)
        #pragma unroll
        for (int j = 0; j < 13; ++j)
            vals[j] += __shfl_down_sync(0xffffffffu, vals[j], off);

    if (lane == 0) {
        #pragma unroll
        for (int j = 0; j < 13; ++j) red[wy * 13 + j] = vals[j];
    }
    __syncthreads();
    const int blockid = blockIdx.x + GYB * blockIdx.y + (GYB * GZB) * blockIdx.z;
    if (tid < 13) {
        float s = 0.f;
        #pragma unroll
        for (int w = 0; w < TY; ++w) s += red[w * 13 + tid];
        g_part[blockid * 13 + tid] = s;
    }

    // ---- deterministic last-block finalize (512 entries) ----
    __threadfence();
    if (tid == 0) amLast = (atomicAdd(&g_count, 1u) == (unsigned)(NBLK - 1)) ? 1u : 0u;
    __syncthreads();
    if (amLast) {
        __threadfence();                   // acquire all g_part writes
        if (tid == 0) g_count = 0;         // reset for next graph replay
        // entries 0..255 -> batch 0, 256..511 -> batch 1 (blockid = .. + 256*bz)
        float v[26];
        const float* p0 = &g_part[tid * 13];
        const float* p1 = &g_part[(tid + 256) * 13];
        #pragma unroll
        for (int j = 0; j < 13; ++j) { v[j] = p0[j]; v[13 + j] = p1[j]; }
        #pragma unroll
        for (int off = 16; off; off >>= 1)
            #pragma unroll
            for (int j = 0; j < 26; ++j)
                v[j] += __shfl_down_sync(0xffffffffu, v[j], off);
        if (lane == 0) {
            #pragma unroll
            for (int j = 0; j < 26; ++j) red[wy * 26 + j] = v[j];
        }
        __syncthreads();
        if (tid == 0) {
            float J1 = 0.f, J2t = 0.f;
            #pragma unroll
            for (int b2 = 0; b2 < 2; ++b2) {
                float s[13];
                #pragma unroll
                for (int j = 0; j < 13; ++j) {
                    float acc = 0.f;
                    #pragma unroll
                    for (int w = 0; w < TY; ++w) acc += red[w * 26 + b2 * 13 + j];
                    s[j] = acc;
                }
                #pragma unroll
                for (int k = 0; k < 4; ++k)
                    J1 += s[k] - s[4 + k] * s[4 + k] / s[8 + k];
                J2t += s[12];
            }
            out[0] = (J1 + 0.0008f * J2t) * (1.0f / (2.0f * (float)NVOX));
        }
    }
}

extern "C" void kernel_launch(void* const* d_in, const int* in_sizes, int n_in,
                              void* d_out, int out_size) {
    const float* yp  = (const float*)d_in[0];  // y_pred [2,4,128,128,128] f32
    const float* img = (const float*)d_in[1];  // image  [2,1,128,128,128] f32
    float* out = (float*)d_out;                // scalar f32

    rfcm<<<dim3(GYB, GZB, 2), dim3(32, TY)>>>(yp, img, out);
}

// round 15
// speedup vs baseline: 1.3203x; 1.1488x over previous
#include <cuda_runtime.h>
#include <cuda_bf16.h>

// RFCM loss, fused single-pass, separable + z-adjoint formulation, f32x2 packed.
//   mem = y_pred^2
//   J1 total = sum_{b,k} (A - B^2/C),  A=Σ mem*img^2, B=Σ mem*img, C=Σ mem
//   J2 = Σ_z [ BS(z)·M3S(z) − MS(z)² − Σ_k b_k(z)·m3_k(z) + Σ_k m_k(z)² ]
//     b_k = 2D 3x3 box at plane z, m3_k(z) = m_k(z−1)+m_k(z)+m_k(z+1)
//   out = (ΣJ1 + 8e-4·ΣJ2) / (B*N)
//
// R10 structure (proven): warp = full x row (32 lanes × float4), x 3-tap via
// shuffles, rowsums in double-buffered smem, y 3-tap via LDS.128, z register
// history, one-plane prefetch, f32x2 packed math, full unroll, CZ=16.
// This round: (1) own-row rowsum kept in regs -> colsum reads only 2 neighbor
// rows (8 LDS); (2) prologue/epilogue planes need only center memberships ->
// lightweight centers() (4 LDG, no rowsum/STS/barrier/halo) instead of full
// commits (their rowsums were provably never read). Barriers 18 -> 16.

namespace {
constexpr int TY   = 8;
constexpr int CZ   = 16;
constexpr int NTH  = 32 * TY;         // 256
constexpr int NVOX = 128 * 128 * 128;
constexpr int PL   = 128 * 128;       // z-plane stride (floats)
constexpr int GYB  = 128 / TY;        // 16
constexpr int GZB  = 128 / CZ;        // 8
constexpr int NBLK = GYB * GZB * 2;   // 256
}

__device__ float g_part[NBLK * 13];
__device__ unsigned int g_count;      // zero-init; reset by finalizer each launch

// ---- packed f32x2 helpers (sm_103a FFMA2 path; PTX-only) ----
struct P2 { unsigned long long v; };
struct Q  { P2 a, b; };               // a = lanes (0,1), b = lanes (2,3)

__device__ __forceinline__ P2 pk(float lo, float hi) {
    P2 r; asm("mov.b64 %0, {%1, %2};" : "=l"(r.v) : "f"(lo), "f"(hi)); return r;
}
__device__ __forceinline__ void upk(P2 a, float& lo, float& hi) {
    asm("mov.b64 {%0, %1}, %2;" : "=f"(lo), "=f"(hi) : "l"(a.v));
}
__device__ __forceinline__ P2 padd(P2 a, P2 b) {
    P2 r; asm("add.rn.f32x2 %0, %1, %2;" : "=l"(r.v) : "l"(a.v), "l"(b.v)); return r;
}
__device__ __forceinline__ P2 pmul(P2 a, P2 b) {
    P2 r; asm("mul.rn.f32x2 %0, %1, %2;" : "=l"(r.v) : "l"(a.v), "l"(b.v)); return r;
}
__device__ __forceinline__ P2 pfma(P2 a, P2 b, P2 c) {
    P2 r; asm("fma.rn.f32x2 %0, %1, %2, %3;"
              : "=l"(r.v) : "l"(a.v), "l"(b.v), "l"(c.v)); return r;
}
__device__ __forceinline__ P2 pneg(P2 a) {
    P2 r; asm("xor.b64 %0, %1, 0x8000000080000000;" : "=l"(r.v) : "l"(a.v)); return r;
}
__device__ __forceinline__ P2 pzero() { P2 r; r.v = 0ull; return r; }
__device__ __forceinline__ float psum(P2 a) { float lo, hi; upk(a, lo, hi); return lo + hi; }
__device__ __forceinline__ P2 u2a(ulonglong2 u) { P2 r; r.v = u.x; return r; }
__device__ __forceinline__ P2 u2b(ulonglong2 u) { P2 r; r.v = u.y; return r; }

__global__ void __launch_bounds__(NTH, 2)
rfcm(const float* __restrict__ yp, const float* __restrict__ img,
     float* __restrict__ out) {
    __shared__ __align__(16) float sb[2][4][TY + 2][128];  // rowsum planes, 2-buf
    __shared__ unsigned amLast;
    const int lane = threadIdx.x, wy = threadIdx.y;
    const int tid  = wy * 32 + lane;
    const int gy0  = blockIdx.x * TY;
    const int z0   = blockIdx.y * CZ;
    const int b    = blockIdx.z;
    const int x0   = lane * 4;
    // halo: 2 rows × 4 clusters = 8 units, one per warp → zero divergence
    const int  hk   = wy & 3;
    const int  hrow = (wy < 4) ? 0 : (TY + 1);
    const int  hy   = (wy < 4) ? (gy0 - 1) : (gy0 + TY);
    const bool hin  = ((unsigned)hy < 128u);

    const float* ypb = yp  + (size_t)b * 4 * NVOX;
    const float* pc[4];
    #pragma unroll
    for (int k = 0; k < 4; ++k)
        pc[k] = ypb + (size_t)k * NVOX + (size_t)(gy0 + wy) * 128 + x0;
    const float* ph  = ypb + (size_t)hk * NVOX + (size_t)(hin ? hy : 0) * 128 + x0;
    const float* pim = img + (size_t)b * NVOX + (size_t)(gy0 + wy) * 128 + x0;

    float4 rc[4], rh;                 // prefetched raw plane
    auto issue = [&](int zp) {        // zp always in [0,128) on this path
        #pragma unroll
        for (int k = 0; k < 4; ++k)
            rc[k] = __ldg(reinterpret_cast<const float4*>(pc[k] + (size_t)zp * PL));
        rh = hin ? __ldg(reinterpret_cast<const float4*>(ph + (size_t)zp * PL))
                 : make_float4(0.f, 0.f, 0.f, 0.f);
    };
    auto centers = [&](int zp, Q m[4]) {   // z-halo plane: center memberships only
        const bool zin = ((unsigned)zp < 128u);
        #pragma unroll
        for (int k = 0; k < 4; ++k) {
            float4 u = zin ? __ldg(reinterpret_cast<const float4*>(pc[k] + (size_t)zp * PL))
                           : make_float4(0.f, 0.f, 0.f, 0.f);
            m[k].a = pk(u.x * u.x, u.y * u.y);
            m[k].b = pk(u.z * u.z, u.w * u.w);
        }
    };
    auto ldimg = [&](int zp) -> Q {
        ulonglong2 u = __ldg(reinterpret_cast<const ulonglong2*>(pim + (size_t)zp * PL));
        Q q; q.a = u2a(u); q.b = u2b(u); return q;
    };
    auto rowsum4 = [&](float x, float y, float z, float w) -> float4 {
        float left  = __shfl_up_sync(0xffffffffu, w, 1);
        float right = __shfl_down_sync(0xffffffffu, x, 1);
        if (lane == 0)  left  = 0.f;
        if (lane == 31) right = 0.f;
        float t1 = x + y, t2 = z + w;
        return make_float4(left + t1, t1 + z, y + t2, t2 + right);
    };
    // square + rowsum + store + 1 barrier; own-row rowsum also kept in regs
    auto commit = [&](int par, Q mnew[4], Q rsown[4]) {
        #pragma unroll
        for (int k = 0; k < 4; ++k) {
            float x = rc[k].x * rc[k].x, y = rc[k].y * rc[k].y;
            float z = rc[k].z * rc[k].z, w = rc[k].w * rc[k].w;
            float4 rs = rowsum4(x, y, z, w);
            *reinterpret_cast<float4*>(&sb[par][k][wy + 1][x0]) = rs;
            rsown[k].a = pk(rs.x, rs.y); rsown[k].b = pk(rs.z, rs.w);
            mnew[k].a = pk(x, y); mnew[k].b = pk(z, w);
        }
        *reinterpret_cast<float4*>(&sb[par][hk][hrow][x0]) =
            rowsum4(rh.x * rh.x, rh.y * rh.y, rh.z * rh.z, rh.w * rh.w);
        __syncthreads();
    };
    // 2D box = own rowsum (regs) + two neighbor rows (smem): 8 LDS.128
    auto colsum = [&](int par, const Q rsown[4], Q bo[4]) {
        #pragma unroll
        for (int k = 0; k < 4; ++k) {
            ulonglong2 r0 = *reinterpret_cast<const ulonglong2*>(&sb[par][k][wy][x0]);
            ulonglong2 r2 = *reinterpret_cast<const ulonglong2*>(&sb[par][k][wy + 2][x0]);
            bo[k].a = padd(padd(u2a(r0), u2a(r2)), rsown[k].a);
            bo[k].b = padd(padd(u2b(r0), u2b(r2)), rsown[k].b);
        }
    };

    Q m1[4], m2[4], bprev[4], mhalo[4];
    #pragma unroll
    for (int k = 0; k < 4; ++k) {
        m1[k].a = pzero(); m1[k].b = pzero();
        bprev[k].a = pzero(); bprev[k].b = pzero();
    }
    P2 A2[4], B2[4], C2[4];
    #pragma unroll
    for (int k = 0; k < 4; ++k) { A2[k] = pzero(); B2[k] = pzero(); C2[k] = pzero(); }
    P2 j2a = pzero(), j2b = pzero();

    auto j2step = [&](const Q mnext[4]) {  // J2 at z: bprev=b(z), m2=m(z), m1=m(z-1)
        P2 M3a = pzero(), M3b = pzero(), BSa = pzero(), BSb = pzero();
        P2 MSa = pzero(), MSb = pzero();
        P2 t1a = pzero(), t1b = pzero(), t2a = pzero(), t2b = pzero();
        #pragma unroll
        for (int k = 0; k < 4; ++k) {
            P2 m3a = padd(padd(m1[k].a, m2[k].a), mnext[k].a);
            P2 m3b = padd(padd(m1[k].b, m2[k].b), mnext[k].b);
            M3a = padd(M3a, m3a);          M3b = padd(M3b, m3b);
            BSa = padd(BSa, bprev[k].a);   BSb = padd(BSb, bprev[k].b);
            MSa = padd(MSa, m2[k].a);      MSb = padd(MSb, m2[k].b);
            t1a = pfma(bprev[k].a, m3a, t1a); t1b = pfma(bprev[k].b, m3b, t1b);
            t2a = pfma(m2[k].a, m2[k].a, t2a); t2b = pfma(m2[k].b, m2[k].b, t2b);
        }
        j2a = pfma(BSa, M3a, j2a); j2a = pfma(pneg(MSa), MSa, j2a);
        j2a = padd(j2a, padd(t2a, pneg(t1a)));
        j2b = pfma(BSb, M3b, j2b); j2b = pfma(pneg(MSb), MSb, j2b);
        j2b = padd(j2b, padd(t2b, pneg(t1b)));
    };

    // prologue: z0-1 centers only (no rowsum/STS/barrier), prefetch z0 + img(z0)
    centers(z0 - 1, m2);              // m2 = m(z0-1)
    issue(z0);
    Q imgc = ldimg(z0);
    Q imgn; imgn.a = pzero(); imgn.b = pzero();

    #pragma unroll
    for (int i = 0; i < CZ; ++i) {    // p = z0 + i : plane being committed
        const int p   = z0 + i;
        const int par = i & 1;

        Q mnew[4], rsown[4];
        commit(par, mnew, rsown);     // consume prefetched raw(p)
        if (i < CZ - 1) {
            issue(p + 1);             // prefetch raw(p+1)
            imgn = ldimg(p + 1);
        } else {
            centers(z0 + CZ, mhalo);  // epilogue z-halo: centers only
        }

        {                             // ABC at plane p
            P2 i2a = pmul(imgc.a, imgc.a), i2b = pmul(imgc.b, imgc.b);
            #pragma unroll
            for (int k = 0; k < 4; ++k) {
                C2[k] = padd(C2[k], padd(mnew[k].a, mnew[k].b));
                B2[k] = pfma(mnew[k].a, imgc.a, pfma(mnew[k].b, imgc.b, B2[k]));
                A2[k] = pfma(mnew[k].a, i2a,    pfma(mnew[k].b, i2b,    A2[k]));
            }
        }
        if (i > 0) j2step(mnew);      // J2 at z = p-1 (bprev=b(p-1), m2=m(p-1))
        colsum(par, rsown, bprev);    // b(p) overwrites bprev
        #pragma unroll
        for (int k = 0; k < 4; ++k) { m1[k] = m2[k]; m2[k] = mnew[k]; }
        imgc = imgn;
    }
    j2step(mhalo);                    // J2 at z0+CZ-1 (needs m(z0+CZ) centers)

    // ---- block reduction: 13 scalars ----
    float vals[13];
    #pragma unroll
    for (int k = 0; k < 4; ++k) {
        vals[k]     = psum(A2[k]);
        vals[4 + k] = psum(B2[k]);
        vals[8 + k] = psum(C2[k]);
    }
    vals[12] = psum(j2a) + psum(j2b);
    #pragma unroll
    for (int off = 16; off; off >>= 1)
        #pragma unroll
        for (int j = 0; j < 13; ++j)
            vals[j] += __shfl_down_sync(0xffffffffu, vals[j], off);

    __syncthreads();                       // stencil smem done; reuse as scratch
    float* red = &sb[0][0][0][0];
    if (lane == 0) {
        #pragma unroll
        for (int j = 0; j < 13; ++j) red[wy * 13 + j] = vals[j];
    }
    __syncthreads();
    const int blockid = blockIdx.x + GYB * blockIdx.y + (GYB * GZB) * blockIdx.z;
    if (tid < 13) {
        float s = 0.f;
        #pragma unroll
        for (int w = 0; w < TY; ++w) s += red[w * 13 + tid];
        g_part[blockid * 13 + tid] = s;
    }

    // ---- deterministic last-block finalize ----
    __threadfence();
    if (tid == 0) amLast = (atomicAdd(&g_count, 1u) == (unsigned)(NBLK - 1)) ? 1u : 0u;
    __syncthreads();
    if (amLast) {
        __threadfence();                   // acquire all g_part writes
        if (tid == 0) g_count = 0;         // reset for next graph replay
        float v[13];                       // entry e = tid; 0..127 b0, 128..255 b1
        const float* pp = &g_part[tid * 13];
        #pragma unroll
        for (int j = 0; j < 13; ++j) v[j] = pp[j];
        #pragma unroll
        for (int off = 16; off; off >>= 1)
            #pragma unroll
            for (int j = 0; j < 13; ++j)
                v[j] += __shfl_down_sync(0xffffffffu, v[j], off);
        if (lane == 0) {
            #pragma unroll
            for (int j = 0; j < 13; ++j) red[wy * 13 + j] = v[j];
        }
        __syncthreads();
        if (tid == 0) {
            float J1 = 0.f, J2t = 0.f;
            #pragma unroll
            for (int b2 = 0; b2 < 2; ++b2) {
                float s[13];
                #pragma unroll
                for (int j = 0; j < 13; ++j)
                    s[j] = red[(b2 * 4 + 0) * 13 + j] + red[(b2 * 4 + 1) * 13 + j] +
                           red[(b2 * 4 + 2) * 13 + j] + red[(b2 * 4 + 3) * 13 + j];
                #pragma unroll
                for (int k = 0; k < 4; ++k)
                    J1 += s[k] - s[4 + k] * s[4 + k] / s[8 + k];
                J2t += s[12];
            }
            out[0] = (J1 + 0.0008f * J2t) * (1.0f / (2.0f * (float)NVOX));
        }
    }
}

extern "C" void kernel_launch(void* const* d_in, const int* in_sizes, int n_in,
                              void* d_out, int out_size) {
    const float* yp  = (const float*)d_in[0];  // y_pred [2,4,128,128,128] f32
    const float* img = (const float*)d_in[1];  // image  [2,1,128,128,128] f32
    float* out = (float*)d_out;                // scalar f32

    rfcm<<<dim3(GYB, GZB, 2), dim3(32, TY)>>>(yp, img, out);
}